// round 14
// baseline (speedup 1.0000x reference)
#include <cuda_runtime.h>
#include <cuda_bf16.h>
#include <cuda_fp16.h>
#include <stdint.h>

#define C_DIM 256
#define HW    4096
#define HWF   65536

// ------------------------------ scratch (proven-passing set)
__device__ float g_q[(size_t)2 * C_DIM * HW];
__device__ float g_k[(size_t)2 * C_DIM * HWF];
__device__ float g_v[(size_t)2 * C_DIM * HWF];

// ------------------------------ helpers
__device__ __forceinline__ void mma16816(float* d, const uint32_t* a, const uint32_t* b) {
    asm volatile(
        "mma.sync.aligned.m16n8k16.row.col.f32.f16.f16.f32 "
        "{%0,%1,%2,%3}, {%4,%5,%6,%7}, {%8,%9}, {%0,%1,%2,%3};"
        : "+f"(d[0]), "+f"(d[1]), "+f"(d[2]), "+f"(d[3])
        : "r"(a[0]), "r"(a[1]), "r"(a[2]), "r"(a[3]), "r"(b[0]), "r"(b[1]));
}

// split float pair -> fp16x2 hi (rounded) + fp16x2 lo (residual); f0 in low half
__device__ __forceinline__ void split2h(float f0, float f1, uint32_t& hi, uint32_t& lo) {
    __half2 h2 = __float22half2_rn(make_float2(f0, f1));
    float2 hf = __half22float2(h2);
    __half2 l2 = __float22half2_rn(make_float2(f0 - hf.x, f1 - hf.y));
    hi = *reinterpret_cast<uint32_t*>(&h2);
    lo = *reinterpret_cast<uint32_t*>(&l2);
}
// convert float pair -> fp16x2 (single rounding, no residual)
__device__ __forceinline__ uint32_t cvt2h(float f0, float f1) {
    __half2 h2 = __float22half2_rn(make_float2(f0, f1));
    return *reinterpret_cast<uint32_t*>(&h2);
}

// ------------------------------ warp-MMA GEMM, fp16 2-term split
// Out[bb][ot*128+m][jt*128+n] = (sum_c W[m][c] * F[bb][c][n] + bias[m]) * scale
// A = W as fp16 hi+lo (exact to ~2^-22); B = F as single fp16 (error ~2.8e-4 rms,
// cancels over K=256). 512 threads, 16 warps (4m x 4n), warp tile 32x32,
// CTA tile 128x128, k-chunk 32. Register prefetch -> in-register convert ->
// bf16/fp16 pair-layout smem tiles; MMA phase pure LDS32 + HMMA.
// Per-stage SMEM (29184 B):
//   +0      Acv hi [128m][20 words]  (16 k-pair uint32 + 4 pad)
//   +10240  Acv lo [128m][20 words]
//   +20480  Bcv    [16kp][136 words] (128 n + 8 pad)
#define ACV_LO   10240
#define BCV_HI   20480
#define STG_BYTES 29184
#define SMEM_TOT (2 * STG_BYTES)    // 58368

__global__ __launch_bounds__(512, 1)
void gemm_mma(const float* __restrict__ W, const float* __restrict__ F,
              const float* __restrict__ bias, float* __restrict__ Out,
              int J, float scale) {
    extern __shared__ char smem[];
    const int t = threadIdx.x, lane = t & 31;
    const int wid = t >> 5, wm = wid & 3, wn = wid >> 2;
    const int jt = blockIdx.x, ot = blockIdx.y, bb = blockIdx.z;

    // prefetch coordinates
    const int ra = t >> 2, qa = t & 3;         // A: row 0..127, k-segment of 8
    const int pk = t >> 5, n0 = (t & 31) * 4;  // B: k-pair row 0..15, 4 n-cols
    const float* gA = W + (size_t)(ot * 128 + ra) * C_DIM + qa * 8;
    const float* gB = F + (size_t)bb * C_DIM * J + (size_t)(2 * pk) * J
                    + (size_t)jt * 128 + n0;

    float acc[2][4][4];
#pragma unroll
    for (int mt = 0; mt < 2; mt++)
#pragma unroll
        for (int np = 0; np < 4; np++)
#pragma unroll
            for (int r = 0; r < 4; r++) acc[mt][np][r] = 0.f;

    float4 pa0, pa1, pb0, pb1;
    // prefetch chunk 0
    pa0 = *(const float4*)(gA);
    pa1 = *(const float4*)(gA + 4);
    pb0 = *(const float4*)(gB);
    pb1 = *(const float4*)(gB + J);

    // convert chunk 0 into stage 0
    {
        char* st = smem;
        float av[8] = {pa0.x, pa0.y, pa0.z, pa0.w, pa1.x, pa1.y, pa1.z, pa1.w};
        uint32_t* ah = (uint32_t*)st;
        uint32_t* al = (uint32_t*)(st + ACV_LO);
#pragma unroll
        for (int jj = 0; jj < 4; jj++) {
            int j = (jj + ra) & 3;
            uint32_t hi, lo;
            split2h(av[2 * j], av[2 * j + 1], hi, lo);
            ah[ra * 20 + qa * 4 + j] = hi;
            al[ra * 20 + qa * 4 + j] = lo;
        }
        uint32_t h[4];
        h[0] = cvt2h(pb0.x, pb1.x);
        h[1] = cvt2h(pb0.y, pb1.y);
        h[2] = cvt2h(pb0.z, pb1.z);
        h[3] = cvt2h(pb0.w, pb1.w);
        *(uint4*)(st + BCV_HI + (pk * 136 + n0) * 4) = make_uint4(h[0], h[1], h[2], h[3]);
    }
    __syncthreads();

#pragma unroll 1
    for (int i = 0; i < 8; i++) {
        // ---- issue register prefetch for chunk i+1 (hidden behind MMA phase)
        if (i < 7) {
            pa0 = *(const float4*)(gA + (i + 1) * 32);
            pa1 = *(const float4*)(gA + (i + 1) * 32 + 4);
            pb0 = *(const float4*)(gB + (size_t)((i + 1) * 32) * J);
            pb1 = *(const float4*)(gB + (size_t)((i + 1) * 32 + 1) * J);
        }

        // ---- MMA phase on stage i&1: pure LDS32 + HMMA (2 terms)
        {
            const char* st = smem + (i & 1) * STG_BYTES;
            const uint32_t* Ah = (const uint32_t*)st;
            const uint32_t* Al = (const uint32_t*)(st + ACV_LO);
            const uint32_t* Bh = (const uint32_t*)(st + BCV_HI);
#pragma unroll
            for (int ks = 0; ks < 2; ks++) {
                const int kp0 = ks * 8 + (lane & 3);
                uint32_t ahi[2][4], alo[2][4];
#pragma unroll
                for (int mt = 0; mt < 2; mt++) {
                    int w0 = (wm * 32 + mt * 16 + (lane >> 2)) * 20 + kp0;
                    ahi[mt][0] = Ah[w0];
                    ahi[mt][1] = Ah[w0 + 8 * 20];
                    ahi[mt][2] = Ah[w0 + 4];
                    ahi[mt][3] = Ah[w0 + 8 * 20 + 4];
                    alo[mt][0] = Al[w0];
                    alo[mt][1] = Al[w0 + 8 * 20];
                    alo[mt][2] = Al[w0 + 4];
                    alo[mt][3] = Al[w0 + 8 * 20 + 4];
                }
#pragma unroll
                for (int np = 0; np < 4; np++) {
                    int wb = kp0 * 136 + wn * 32 + np * 8 + (lane >> 2);
                    uint32_t bh[2];
                    bh[0] = Bh[wb];
                    bh[1] = Bh[wb + 4 * 136];
#pragma unroll
                    for (int mt = 0; mt < 2; mt++) {
                        mma16816(acc[mt][np], ahi[mt], bh);   // Ahi*B
                        mma16816(acc[mt][np], alo[mt], bh);   // Alo*B
                    }
                }
            }
        }

        // ---- convert chunk i+1 into the other stage (different buffer: no race)
        if (i < 7) {
            char* st = smem + ((i + 1) & 1) * STG_BYTES;
            float av[8] = {pa0.x, pa0.y, pa0.z, pa0.w, pa1.x, pa1.y, pa1.z, pa1.w};
            uint32_t* ah = (uint32_t*)st;
            uint32_t* al = (uint32_t*)(st + ACV_LO);
#pragma unroll
            for (int jj = 0; jj < 4; jj++) {
                int j = (jj + ra) & 3;
                uint32_t hi, lo;
                split2h(av[2 * j], av[2 * j + 1], hi, lo);
                ah[ra * 20 + qa * 4 + j] = hi;
                al[ra * 20 + qa * 4 + j] = lo;
            }
            uint32_t h[4];
            h[0] = cvt2h(pb0.x, pb1.x);
            h[1] = cvt2h(pb0.y, pb1.y);
            h[2] = cvt2h(pb0.z, pb1.z);
            h[3] = cvt2h(pb0.w, pb1.w);
            *(uint4*)(st + BCV_HI + (pk * 136 + n0) * 4) = make_uint4(h[0], h[1], h[2], h[3]);
        }
        __syncthreads();
    }

    // ---- epilogue: (acc + bias) * scale
#pragma unroll
    for (int mt = 0; mt < 2; mt++)
#pragma unroll
        for (int half = 0; half < 2; half++) {
            int o = ot * 128 + wm * 32 + mt * 16 + half * 8 + (lane >> 2);
            float bi = bias[o];
            float* orow = Out + ((size_t)bb * C_DIM + o) * J
                        + (size_t)jt * 128 + wn * 32 + (lane & 3) * 2;
#pragma unroll
            for (int np = 0; np < 4; np++) {
                float2 v;
                v.x = (acc[mt][np][half * 2 + 0] + bi) * scale;
                v.y = (acc[mt][np][half * 2 + 1] + bi) * scale;
                *(float2*)(orow + np * 8) = v;
            }
        }
}

// ------------------------------ attention, 4 threads per query
// sub-lane (t&3) owns 8 of 32 head-dims; logits butterfly-reduced over lanes
// differing in bits 0..1 (same query), softmax redundant, V gather partial.
__global__ __launch_bounds__(256)
void attn_kernel(const float* __restrict__ q, const float* __restrict__ k,
                 const float* __restrict__ v, float* __restrict__ out) {
    int t = blockIdx.x * blockDim.x + threadIdx.x;   // 262144 threads
    int sub = t & 3;
    int qid = t >> 2;                                // 0..65535
    int x = qid & 63;
    int y = (qid >> 6) & 63;
    int head = (qid >> 12) & 7;
    int b = qid >> 15;

    const size_t chq = (size_t)(b * C_DIM + head * 32) + sub * 8;
    const float* qb = q + chq * HW + y * 64 + x;
    const size_t fbase = chq * HWF + (size_t)(4 * y) * 256 + 4 * x;
    const float* kb = k + fbase;
    const float* vb = v + fbase;

    float logit[16];
#pragma unroll
    for (int p = 0; p < 16; p++) logit[p] = 0.f;

#pragma unroll
    for (int dd = 0; dd < 8; dd++) {
        float qd = qb[(size_t)dd * HW];
#pragma unroll
        for (int dy = 0; dy < 4; dy++) {
            float4 kv = *(const float4*)(kb + (size_t)dd * HWF + dy * 256);
            logit[dy * 4 + 0] = fmaf(qd, kv.x, logit[dy * 4 + 0]);
            logit[dy * 4 + 1] = fmaf(qd, kv.y, logit[dy * 4 + 1]);
            logit[dy * 4 + 2] = fmaf(qd, kv.z, logit[dy * 4 + 2]);
            logit[dy * 4 + 3] = fmaf(qd, kv.w, logit[dy * 4 + 3]);
        }
    }

    // reduce partial logits across the 4 sub-lanes of this query
#pragma unroll
    for (int p = 0; p < 16; p++) {
        logit[p] += __shfl_xor_sync(0xFFFFFFFFu, logit[p], 1);
        logit[p] += __shfl_xor_sync(0xFFFFFFFFu, logit[p], 2);
    }

    float m = logit[0];
#pragma unroll
    for (int p = 1; p < 16; p++) m = fmaxf(m, logit[p]);
    float s = 0.f;
#pragma unroll
    for (int p = 0; p < 16; p++) { logit[p] = __expf(logit[p] - m); s += logit[p]; }
    float inv = 1.f / s;
#pragma unroll
    for (int p = 0; p < 16; p++) logit[p] *= inv;

    float* ob = out + chq * HW + y * 64 + x;
#pragma unroll
    for (int dd = 0; dd < 8; dd++) {
        float sum = 0.f;
#pragma unroll
        for (int dy = 0; dy < 4; dy++) {
            float4 vv = *(const float4*)(vb + (size_t)dd * HWF + dy * 256);
            sum = fmaf(logit[dy * 4 + 0], vv.x, sum);
            sum = fmaf(logit[dy * 4 + 1], vv.y, sum);
            sum = fmaf(logit[dy * 4 + 2], vv.z, sum);
            sum = fmaf(logit[dy * 4 + 3], vv.w, sum);
        }
        ob[(size_t)dd * HW] = sum;
    }
}

// ------------------------------ launch
extern "C" void kernel_launch(void* const* d_in, const int* in_sizes, int n_in,
                              void* d_out, int out_size) {
    const float* x  = (const float*)d_in[0];
    const float* fm = (const float*)d_in[1];
    const float* Wq = (const float*)d_in[2];
    const float* bq = (const float*)d_in[3];
    const float* Wk = (const float*)d_in[4];
    const float* bk = (const float*)d_in[5];
    const float* Wv = (const float*)d_in[6];
    const float* bv = (const float*)d_in[7];
    float* out = (float*)d_out;

    float *q, *k, *v;
    cudaGetSymbolAddress((void**)&q, g_q);
    cudaGetSymbolAddress((void**)&k, g_k);
    cudaGetSymbolAddress((void**)&v, g_v);

    cudaFuncSetAttribute(gemm_mma, cudaFuncAttributeMaxDynamicSharedMemorySize, SMEM_TOT);

    const float scaling = 0.17677669529663687f;  // 32^-0.5

    gemm_mma<<<dim3(HW / 128, 2, 2), 512, SMEM_TOT>>>(Wq, x, bq, q, HW, scaling);
    gemm_mma<<<dim3(HWF / 128, 2, 2), 512, SMEM_TOT>>>(Wk, fm, bk, k, HWF, 1.0f);
    gemm_mma<<<dim3(HWF / 128, 2, 2), 512, SMEM_TOT>>>(Wv, fm, bv, v, HWF, 1.0f);

    attn_kernel<<<(2 * 8 * HW * 4) / 256, 256>>>(q, k, v, out);
}

// round 16
// speedup vs baseline: 1.1314x; 1.1314x over previous
#include <cuda_runtime.h>
#include <cuda_bf16.h>
#include <cuda_fp16.h>
#include <stdint.h>

#define C_DIM 256
#define HW    4096
#define HWF   65536

// ------------------------------ scratch (proven-passing set)
__device__ float g_q[(size_t)2 * C_DIM * HW];
__device__ float g_k[(size_t)2 * C_DIM * HWF];
__device__ float g_v[(size_t)2 * C_DIM * HWF];

// ------------------------------ helpers
__device__ __forceinline__ void mma16816(float* d, const uint32_t* a, const uint32_t* b) {
    asm volatile(
        "mma.sync.aligned.m16n8k16.row.col.f32.f16.f16.f32 "
        "{%0,%1,%2,%3}, {%4,%5,%6,%7}, {%8,%9}, {%0,%1,%2,%3};"
        : "+f"(d[0]), "+f"(d[1]), "+f"(d[2]), "+f"(d[3])
        : "r"(a[0]), "r"(a[1]), "r"(a[2]), "r"(a[3]), "r"(b[0]), "r"(b[1]));
}

// convert float pair -> fp16x2 (single rounding); f0 in low half
__device__ __forceinline__ uint32_t cvt2h(float f0, float f1) {
    __half2 h2 = __float22half2_rn(make_float2(f0, f1));
    return *reinterpret_cast<uint32_t*>(&h2);
}

// ------------------------------ warp-MMA GEMM, single-term fp16
// Out[bb][ot*128+m][jt*128+n] = (sum_c W[m][c] * F[bb][c][n] + bias[m]) * scale
// Both operands single-rounded fp16 (measured B-only error 3.2e-4; A adds an
// independent equal term -> ~4.6e-4 combined, 2x margin under 1e-3).
// 512 threads, 16 warps (4m x 4n), warp tile 32x32, CTA tile 128x128, k-chunk 32.
// Register prefetch -> in-register convert -> fp16 pair-layout smem tiles;
// MMA phase pure LDS32 + HMMA. One __syncthreads per chunk; ping-pong stages.
// Per-stage SMEM (18944 B):
//   +0      Acv [128m][20 words]  (16 k-pair uint32 + 4 pad)
//   +10240  Bcv [16kp][136 words] (128 n + 8 pad)
#define BCV_OFF  10240
#define STG_BYTES 18944
#define SMEM_TOT (2 * STG_BYTES)    // 37888

__global__ __launch_bounds__(512, 1)
void gemm_mma(const float* __restrict__ W, const float* __restrict__ F,
              const float* __restrict__ bias, float* __restrict__ Out,
              int J, float scale) {
    extern __shared__ char smem[];
    const int t = threadIdx.x, lane = t & 31;
    const int wid = t >> 5, wm = wid & 3, wn = wid >> 2;
    const int jt = blockIdx.x, ot = blockIdx.y, bb = blockIdx.z;

    // prefetch coordinates
    const int ra = t >> 2, qa = t & 3;         // A: row 0..127, k-segment of 8
    const int pk = t >> 5, n0 = (t & 31) * 4;  // B: k-pair row 0..15, 4 n-cols
    const float* gA = W + (size_t)(ot * 128 + ra) * C_DIM + qa * 8;
    const float* gB = F + (size_t)bb * C_DIM * J + (size_t)(2 * pk) * J
                    + (size_t)jt * 128 + n0;

    float acc[2][4][4];
#pragma unroll
    for (int mt = 0; mt < 2; mt++)
#pragma unroll
        for (int np = 0; np < 4; np++)
#pragma unroll
            for (int r = 0; r < 4; r++) acc[mt][np][r] = 0.f;

    float4 pa0, pa1, pb0, pb1;
    // prefetch chunk 0
    pa0 = *(const float4*)(gA);
    pa1 = *(const float4*)(gA + 4);
    pb0 = *(const float4*)(gB);
    pb1 = *(const float4*)(gB + J);

    // convert chunk 0 into stage 0
    {
        char* st = smem;
        float av[8] = {pa0.x, pa0.y, pa0.z, pa0.w, pa1.x, pa1.y, pa1.z, pa1.w};
        uint32_t* ah = (uint32_t*)st;
#pragma unroll
        for (int jj = 0; jj < 4; jj++) {
            int j = (jj + ra) & 3;
            ah[ra * 20 + qa * 4 + j] = cvt2h(av[2 * j], av[2 * j + 1]);
        }
        uint32_t h[4];
        h[0] = cvt2h(pb0.x, pb1.x);
        h[1] = cvt2h(pb0.y, pb1.y);
        h[2] = cvt2h(pb0.z, pb1.z);
        h[3] = cvt2h(pb0.w, pb1.w);
        *(uint4*)(st + BCV_OFF + (pk * 136 + n0) * 4) = make_uint4(h[0], h[1], h[2], h[3]);
    }
    __syncthreads();

#pragma unroll 1
    for (int i = 0; i < 8; i++) {
        // ---- issue register prefetch for chunk i+1 (hidden behind MMA phase)
        if (i < 7) {
            pa0 = *(const float4*)(gA + (i + 1) * 32);
            pa1 = *(const float4*)(gA + (i + 1) * 32 + 4);
            pb0 = *(const float4*)(gB + (size_t)((i + 1) * 32) * J);
            pb1 = *(const float4*)(gB + (size_t)((i + 1) * 32 + 1) * J);
        }

        // ---- MMA phase on stage i&1: pure LDS32 + HMMA (1 term)
        {
            const char* st = smem + (i & 1) * STG_BYTES;
            const uint32_t* Ah = (const uint32_t*)st;
            const uint32_t* Bh = (const uint32_t*)(st + BCV_OFF);
#pragma unroll
            for (int ks = 0; ks < 2; ks++) {
                const int kp0 = ks * 8 + (lane & 3);
                uint32_t ahi[2][4];
#pragma unroll
                for (int mt = 0; mt < 2; mt++) {
                    int w0 = (wm * 32 + mt * 16 + (lane >> 2)) * 20 + kp0;
                    ahi[mt][0] = Ah[w0];
                    ahi[mt][1] = Ah[w0 + 8 * 20];
                    ahi[mt][2] = Ah[w0 + 4];
                    ahi[mt][3] = Ah[w0 + 8 * 20 + 4];
                }
#pragma unroll
                for (int np = 0; np < 4; np++) {
                    int wb = kp0 * 136 + wn * 32 + np * 8 + (lane >> 2);
                    uint32_t bh[2];
                    bh[0] = Bh[wb];
                    bh[1] = Bh[wb + 4 * 136];
#pragma unroll
                    for (int mt = 0; mt < 2; mt++)
                        mma16816(acc[mt][np], ahi[mt], bh);
                }
            }
        }

        // ---- convert chunk i+1 into the other stage (different buffer: no race)
        if (i < 7) {
            char* st = smem + ((i + 1) & 1) * STG_BYTES;
            float av[8] = {pa0.x, pa0.y, pa0.z, pa0.w, pa1.x, pa1.y, pa1.z, pa1.w};
            uint32_t* ah = (uint32_t*)st;
#pragma unroll
            for (int jj = 0; jj < 4; jj++) {
                int j = (jj + ra) & 3;
                ah[ra * 20 + qa * 4 + j] = cvt2h(av[2 * j], av[2 * j + 1]);
            }
            uint32_t h[4];
            h[0] = cvt2h(pb0.x, pb1.x);
            h[1] = cvt2h(pb0.y, pb1.y);
            h[2] = cvt2h(pb0.z, pb1.z);
            h[3] = cvt2h(pb0.w, pb1.w);
            *(uint4*)(st + BCV_OFF + (pk * 136 + n0) * 4) = make_uint4(h[0], h[1], h[2], h[3]);
        }
        __syncthreads();
    }

    // ---- epilogue: (acc + bias) * scale
#pragma unroll
    for (int mt = 0; mt < 2; mt++)
#pragma unroll
        for (int half = 0; half < 2; half++) {
            int o = ot * 128 + wm * 32 + mt * 16 + half * 8 + (lane >> 2);
            float bi = bias[o];
            float* orow = Out + ((size_t)bb * C_DIM + o) * J
                        + (size_t)jt * 128 + wn * 32 + (lane & 3) * 2;
#pragma unroll
            for (int np = 0; np < 4; np++) {
                float2 v;
                v.x = (acc[mt][np][half * 2 + 0] + bi) * scale;
                v.y = (acc[mt][np][half * 2 + 1] + bi) * scale;
                *(float2*)(orow + np * 8) = v;
            }
        }
}

// ------------------------------ attention, 8 threads per query
// sub-lane (t&7) owns 4 of 32 head-dims; logits butterfly-reduced over lanes
// differing in bits 0..2 (same query), softmax redundant, V gather partial.
__global__ __launch_bounds__(256)
void attn_kernel(const float* __restrict__ q, const float* __restrict__ k,
                 const float* __restrict__ v, float* __restrict__ out) {
    int t = blockIdx.x * blockDim.x + threadIdx.x;   // 524288 threads
    int sub = t & 7;
    int qid = t >> 3;                                // 0..65535
    int x = qid & 63;
    int y = (qid >> 6) & 63;
    int head = (qid >> 12) & 7;
    int b = qid >> 15;

    const size_t chq = (size_t)(b * C_DIM + head * 32) + sub * 4;
    const float* qb = q + chq * HW + y * 64 + x;
    const size_t fbase = chq * HWF + (size_t)(4 * y) * 256 + 4 * x;
    const float* kb = k + fbase;
    const float* vb = v + fbase;

    float logit[16];
#pragma unroll
    for (int p = 0; p < 16; p++) logit[p] = 0.f;

#pragma unroll
    for (int dd = 0; dd < 4; dd++) {
        float qd = qb[(size_t)dd * HW];
#pragma unroll
        for (int dy = 0; dy < 4; dy++) {
            float4 kv = *(const float4*)(kb + (size_t)dd * HWF + dy * 256);
            logit[dy * 4 + 0] = fmaf(qd, kv.x, logit[dy * 4 + 0]);
            logit[dy * 4 + 1] = fmaf(qd, kv.y, logit[dy * 4 + 1]);
            logit[dy * 4 + 2] = fmaf(qd, kv.z, logit[dy * 4 + 2]);
            logit[dy * 4 + 3] = fmaf(qd, kv.w, logit[dy * 4 + 3]);
        }
    }

    // reduce partial logits across the 8 sub-lanes of this query
#pragma unroll
    for (int p = 0; p < 16; p++) {
        logit[p] += __shfl_xor_sync(0xFFFFFFFFu, logit[p], 1);
        logit[p] += __shfl_xor_sync(0xFFFFFFFFu, logit[p], 2);
        logit[p] += __shfl_xor_sync(0xFFFFFFFFu, logit[p], 4);
    }

    float m = logit[0];
#pragma unroll
    for (int p = 1; p < 16; p++) m = fmaxf(m, logit[p]);
    float s = 0.f;
#pragma unroll
    for (int p = 0; p < 16; p++) { logit[p] = __expf(logit[p] - m); s += logit[p]; }
    float inv = 1.f / s;
#pragma unroll
    for (int p = 0; p < 16; p++) logit[p] *= inv;

    float* ob = out + chq * HW + y * 64 + x;
#pragma unroll
    for (int dd = 0; dd < 4; dd++) {
        float sum = 0.f;
#pragma unroll
        for (int dy = 0; dy < 4; dy++) {
            float4 vv = *(const float4*)(vb + (size_t)dd * HWF + dy * 256);
            sum = fmaf(logit[dy * 4 + 0], vv.x, sum);
            sum = fmaf(logit[dy * 4 + 1], vv.y, sum);
            sum = fmaf(logit[dy * 4 + 2], vv.z, sum);
            sum = fmaf(logit[dy * 4 + 3], vv.w, sum);
        }
        ob[(size_t)dd * HW] = sum;
    }
}

// ------------------------------ launch
extern "C" void kernel_launch(void* const* d_in, const int* in_sizes, int n_in,
                              void* d_out, int out_size) {
    const float* x  = (const float*)d_in[0];
    const float* fm = (const float*)d_in[1];
    const float* Wq = (const float*)d_in[2];
    const float* bq = (const float*)d_in[3];
    const float* Wk = (const float*)d_in[4];
    const float* bk = (const float*)d_in[5];
    const float* Wv = (const float*)d_in[6];
    const float* bv = (const float*)d_in[7];
    float* out = (float*)d_out;

    float *q, *k, *v;
    cudaGetSymbolAddress((void**)&q, g_q);
    cudaGetSymbolAddress((void**)&k, g_k);
    cudaGetSymbolAddress((void**)&v, g_v);

    cudaFuncSetAttribute(gemm_mma, cudaFuncAttributeMaxDynamicSharedMemorySize, SMEM_TOT);

    const float scaling = 0.17677669529663687f;  // 32^-0.5

    gemm_mma<<<dim3(HW / 128, 2, 2), 512, SMEM_TOT>>>(Wq, x, bq, q, HW, scaling);
    gemm_mma<<<dim3(HWF / 128, 2, 2), 512, SMEM_TOT>>>(Wk, fm, bk, k, HWF, 1.0f);
    gemm_mma<<<dim3(HWF / 128, 2, 2), 512, SMEM_TOT>>>(Wv, fm, bv, v, HWF, 1.0f);

    attn_kernel<<<(2 * 8 * HW * 8) / 256, 256>>>(q, k, v, out);
}